// round 3
// baseline (speedup 1.0000x reference)
#include <cuda_runtime.h>

#define N_NODES 100000
#define HID 64
#define EPS 1e-5f

// Scratch (allocation-free rule: __device__ globals)
__device__ float g_dinv[N_NODES];            // deg -> rsqrt(deg)
__device__ float g_hw [N_NODES * HID];       // h @ W
__device__ float g_agg[N_NODES * HID];       // aggregated messages
__device__ float g_h  [N_NODES * HID];       // post-BN activations
__device__ float g_stats[2 * HID];           // per-channel sum / sumsq

// ---------------- degree / norm ----------------
__global__ void k_init_deg() {
    int i = blockIdx.x * blockDim.x + threadIdx.x;
    if (i < N_NODES) g_dinv[i] = 1.0f;   // self loop
}

__global__ void k_count_deg(const int* __restrict__ dst, int E) {
    int i = blockIdx.x * blockDim.x + threadIdx.x;
    if (i < E) atomicAdd(&g_dinv[dst[i]], 1.0f);
}

__global__ void k_finish_deg() {
    int i = blockIdx.x * blockDim.x + threadIdx.x;
    if (i < N_NODES) g_dinv[i] = rsqrtf(g_dinv[i]);
}

// ---------------- dense GEMM: out = in @ W  (W in smem, one row/thread) ----
__global__ void k_gemm(const float* __restrict__ x, const float* __restrict__ W,
                       int fi, int use_x) {
    extern __shared__ float sW[];                 // fi * HID
    for (int i = threadIdx.x; i < fi * HID; i += blockDim.x) sW[i] = W[i];
    __syncthreads();

    int row = blockIdx.x * blockDim.x + threadIdx.x;
    if (row >= N_NODES) return;

    const float* in = use_x ? x : g_h;
    const float* r = in + (size_t)row * fi;

    float acc[HID];
#pragma unroll
    for (int j = 0; j < HID; j++) acc[j] = 0.0f;

    for (int k = 0; k < fi; k++) {
        float v = __ldg(r + k);
        const float4* w4 = (const float4*)(sW + k * HID);
#pragma unroll
        for (int j = 0; j < HID / 4; j++) {
            float4 w = w4[j];
            acc[4 * j + 0] += v * w.x;
            acc[4 * j + 1] += v * w.y;
            acc[4 * j + 2] += v * w.z;
            acc[4 * j + 3] += v * w.w;
        }
    }

    float4* o = (float4*)(g_hw + (size_t)row * HID);
#pragma unroll
    for (int j = 0; j < HID / 4; j++)
        o[j] = make_float4(acc[4 * j], acc[4 * j + 1], acc[4 * j + 2], acc[4 * j + 3]);
}

// ---------------- agg init: bias + self-loop contribution -----------------
__global__ void k_agg_init(const float* __restrict__ b) {
    int idx = blockIdx.x * blockDim.x + threadIdx.x;      // float4 index
    if (idx >= N_NODES * (HID / 4)) return;
    int node = idx / (HID / 4);
    int j4   = idx % (HID / 4);
    float dv = g_dinv[node];
    float s  = dv * dv;
    float4 h  = ((const float4*)g_hw)[idx];
    float4 bb = ((const float4*)b)[j4];
    float4 r;
    r.x = bb.x + h.x * s; r.y = bb.y + h.y * s;
    r.z = bb.z + h.z * s; r.w = bb.w + h.w * s;
    ((float4*)g_agg)[idx] = r;
}

// ---------------- edge scatter: 16 lanes per edge, vectorized REDG --------
__global__ void k_scatter(const int* __restrict__ src,
                          const int* __restrict__ dst, int E) {
    int t = blockIdx.x * blockDim.x + threadIdx.x;
    int e = t >> 4;
    if (e >= E) return;
    int l = t & 15;
    int s = src[e];
    int d = dst[e];
    float nrm = g_dinv[s] * g_dinv[d];
    float4 v = *(((const float4*)(g_hw + (size_t)s * HID)) + l);
    v.x *= nrm; v.y *= nrm; v.z *= nrm; v.w *= nrm;
    float* a = (float*)(((float4*)(g_agg + (size_t)d * HID)) + l);
    asm volatile("red.global.add.v4.f32 [%0], {%1, %2, %3, %4};"
                 :: "l"(a), "f"(v.x), "f"(v.y), "f"(v.z), "f"(v.w) : "memory");
}

// ---------------- batch-norm stats --------------------------------------
__global__ void k_zero_stats() {
    if (threadIdx.x < 2 * HID) g_stats[threadIdx.x] = 0.0f;
}

__global__ void k_reduce_stats() {
    __shared__ float ss[256], sq[256];
    int j  = threadIdx.x & 63;       // channel
    int rg = threadIdx.x >> 6;       // row group (0..3)
    float s = 0.0f, q = 0.0f;
    for (int r = blockIdx.x * 4 + rg; r < N_NODES; r += gridDim.x * 4) {
        float v = g_agg[(size_t)r * HID + j];
        s += v; q += v * v;
    }
    ss[threadIdx.x] = s; sq[threadIdx.x] = q;
    __syncthreads();
    if (threadIdx.x < 64) {
        float S = ss[threadIdx.x] + ss[threadIdx.x + 64] + ss[threadIdx.x + 128] + ss[threadIdx.x + 192];
        float Q = sq[threadIdx.x] + sq[threadIdx.x + 64] + sq[threadIdx.x + 128] + sq[threadIdx.x + 192];
        atomicAdd(&g_stats[j], S);
        atomicAdd(&g_stats[HID + j], Q);
    }
}

__global__ void k_bn_relu(const float* __restrict__ g, const float* __restrict__ bt) {
    int idx = blockIdx.x * blockDim.x + threadIdx.x;
    if (idx >= N_NODES * HID) return;
    int j = idx & 63;
    const float invN = 1.0f / (float)N_NODES;
    float mu  = g_stats[j] * invN;
    float var = g_stats[HID + j] * invN - mu * mu;
    float sc  = rsqrtf(var + EPS) * g[j];
    float v = (g_agg[idx] - mu) * sc + bt[j];
    g_h[idx] = v > 0.0f ? v : 0.0f;
}

// ---------------- MLP head ------------------------------------------------
__global__ void k_mlp(const float* __restrict__ lw1, const float* __restrict__ lb1,
                      const float* __restrict__ lw2, const float* __restrict__ lb2,
                      float* __restrict__ out) {
    __shared__ float sW1[64 * 32];
    __shared__ float sW2[32];
    __shared__ float sB1[32];
    __shared__ float sB2;
    for (int i = threadIdx.x; i < 64 * 32; i += blockDim.x) sW1[i] = lw1[i];
    if (threadIdx.x < 32) { sW2[threadIdx.x] = lw2[threadIdx.x]; sB1[threadIdx.x] = lb1[threadIdx.x]; }
    if (threadIdx.x == 0) sB2 = lb2[0];
    __syncthreads();

    int n = blockIdx.x * blockDim.x + threadIdx.x;
    if (n >= N_NODES) return;

    float t[32];
#pragma unroll
    for (int j = 0; j < 32; j++) t[j] = sB1[j];
    const float* h = g_h + (size_t)n * HID;
    for (int k = 0; k < 64; k++) {
        float v = h[k];
#pragma unroll
        for (int j = 0; j < 32; j++) t[j] += v * sW1[k * 32 + j];
    }
    float o = sB2;
#pragma unroll
    for (int j = 0; j < 32; j++) {
        float r = t[j] > 0.0f ? t[j] : 0.0f;
        o += r * sW2[j];
    }
    out[n] = o;
}

// ---------------- driver --------------------------------------------------
extern "C" void kernel_launch(void* const* d_in, const int* in_sizes, int n_in,
                              void* d_out, int out_size) {
    const float* x   = (const float*)d_in[0];
    const int*   ei  = (const int*)d_in[1];     // JAX silently downgrades int64->int32
    int E = in_sizes[1] / 2;
    const int* src = ei;
    const int* dst = ei + E;

    const float* W[3]  = { (const float*)d_in[2],  (const float*)d_in[6],  (const float*)d_in[10] };
    const float* B[3]  = { (const float*)d_in[3],  (const float*)d_in[7],  (const float*)d_in[11] };
    const float* G[3]  = { (const float*)d_in[4],  (const float*)d_in[8],  (const float*)d_in[12] };
    const float* BT[3] = { (const float*)d_in[5],  (const float*)d_in[9],  (const float*)d_in[13] };
    const float* lw1 = (const float*)d_in[14];
    const float* lb1 = (const float*)d_in[15];
    const float* lw2 = (const float*)d_in[16];
    const float* lb2 = (const float*)d_in[17];
    float* out = (float*)d_out;

    // degree + normalization
    k_init_deg  <<<(N_NODES + 255) / 256, 256>>>();
    k_count_deg <<<(E + 255) / 256, 256>>>(dst, E);
    k_finish_deg<<<(N_NODES + 255) / 256, 256>>>();

    for (int l = 0; l < 3; l++) {
        int fi = (l == 0) ? 128 : HID;
        k_gemm<<<(N_NODES + 127) / 128, 128, fi * HID * sizeof(float)>>>(x, W[l], fi, l == 0 ? 1 : 0);
        k_agg_init<<<(N_NODES * (HID / 4) + 255) / 256, 256>>>(B[l]);
        k_scatter<<<((size_t)E * 16 + 255) / 256, 256>>>(src, dst, E);
        k_zero_stats<<<1, 2 * HID>>>();
        k_reduce_stats<<<512, 256>>>();
        k_bn_relu<<<(N_NODES * HID + 255) / 256, 256>>>(G[l], BT[l]);
    }

    k_mlp<<<(N_NODES + 255) / 256, 256>>>(lw1, lb1, lw2, lb2, out);
}

// round 8
// speedup vs baseline: 1.3038x; 1.3038x over previous
#include <cuda_runtime.h>

#define N_NODES 100000
#define HID 64
#define EPS 1e-5f

// Scratch (allocation-free rule: __device__ globals)
__device__ float g_dinv[N_NODES];            // deg -> rsqrt(deg)
__device__ float g_hw [N_NODES * HID];       // h @ W
__device__ float g_agg[N_NODES * HID];       // aggregated messages (also next-layer input)
__device__ float g_stats[2 * HID];           // per-channel sum / sumsq
__device__ float g_bnc[2 * HID];             // per-channel BN (scale, shift)

// ---------------- degree / norm ----------------
__global__ void k_init_deg() {
    int i = blockIdx.x * blockDim.x + threadIdx.x;
    if (i < N_NODES) g_dinv[i] = 1.0f;   // self loop
}

__global__ void k_count_deg(const int* __restrict__ dst, int E) {
    int i = blockIdx.x * blockDim.x + threadIdx.x;
    if (i < E) atomicAdd(&g_dinv[dst[i]], 1.0f);
}

__global__ void k_finish_deg() {
    int i = blockIdx.x * blockDim.x + threadIdx.x;
    if (i < N_NODES) g_dinv[i] = rsqrtf(g_dinv[i]);
}

// ---------------- fused GEMM ----------------------------------------------
// hw = act(in) @ W ; g_hw = hw ; g_agg = bias + hw * dinv^2  (self loop)
// act = identity (layer 0, in = x) or BN+ReLU via g_bnc (layers 1,2, in = g_agg).
// Safe in-place: each block reads exactly the g_agg rows it later overwrites.
// BM=128 rows, BN=64 cols, BK=32. 256 threads, each 4 rows x 8 cols.
__global__ void __launch_bounds__(256, 2)
k_gemm_fused(const float* __restrict__ xin, const float* __restrict__ W,
             const float* __restrict__ bias, int fi, int use_bn)
{
    __shared__ float sA[128 * 36];   // [row][k] padded to 36
    __shared__ float sW[32 * 64];    // [k][col]
    __shared__ float sDinv2[128];
    __shared__ float sSc[64], sSh[64], sBias[64];

    const float* in = use_bn ? (const float*)g_agg : xin;

    int tid = threadIdx.x;
    int block_row = blockIdx.x * 128;

    if (tid < 64) {
        sBias[tid] = bias[tid];
        if (use_bn) { sSc[tid] = g_bnc[tid]; sSh[tid] = g_bnc[64 + tid]; }
    }
    if (tid < 128) {
        int r = block_row + tid;
        float dv = (r < N_NODES) ? g_dinv[r] : 0.0f;
        sDinv2[tid] = dv * dv;
    }

    float acc[4][8];
#pragma unroll
    for (int i = 0; i < 4; i++)
#pragma unroll
        for (int j = 0; j < 8; j++) acc[i][j] = 0.0f;

    int ty = tid >> 3;            // 0..31 -> rows ty*4..+4
    int tx = tid & 7;             // 0..7  -> cols tx*8..+8

    for (int k0 = 0; k0 < fi; k0 += 32) {
        __syncthreads();          // also orders sSc/sSh/sDinv2/sBias init on 1st iter
        // load A chunk: 128 rows x 32 cols = 1024 float4
        for (int idx = tid; idx < 128 * 8; idx += 256) {
            int row = idx >> 3;
            int c4  = (idx & 7) * 4;
            int rg  = block_row + row;
            float4 v = make_float4(0.f, 0.f, 0.f, 0.f);
            if (rg < N_NODES)
                v = *(const float4*)(in + (size_t)rg * fi + k0 + c4);
            if (use_bn) {
                int c = k0 + c4;
                v.x = fmaxf(v.x * sSc[c]     + sSh[c],     0.f);
                v.y = fmaxf(v.y * sSc[c + 1] + sSh[c + 1], 0.f);
                v.z = fmaxf(v.z * sSc[c + 2] + sSh[c + 2], 0.f);
                v.w = fmaxf(v.w * sSc[c + 3] + sSh[c + 3], 0.f);
            }
            *(float4*)(sA + row * 36 + c4) = v;
        }
        // load W chunk: 32 x 64
        for (int idx = tid; idx < 32 * 16; idx += 256) {
            int row = idx >> 4;
            int c4  = (idx & 15) * 4;
            *(float4*)(sW + row * 64 + c4) =
                *(const float4*)(W + (size_t)(k0 + row) * 64 + c4);
        }
        __syncthreads();

#pragma unroll
        for (int k = 0; k < 32; k++) {
            float4 b0 = *(const float4*)(sW + k * 64 + tx * 8);
            float4 b1 = *(const float4*)(sW + k * 64 + tx * 8 + 4);
            float a0 = sA[(ty * 4 + 0) * 36 + k];
            float a1 = sA[(ty * 4 + 1) * 36 + k];
            float a2 = sA[(ty * 4 + 2) * 36 + k];
            float a3 = sA[(ty * 4 + 3) * 36 + k];
            acc[0][0] += a0 * b0.x; acc[0][1] += a0 * b0.y; acc[0][2] += a0 * b0.z; acc[0][3] += a0 * b0.w;
            acc[0][4] += a0 * b1.x; acc[0][5] += a0 * b1.y; acc[0][6] += a0 * b1.z; acc[0][7] += a0 * b1.w;
            acc[1][0] += a1 * b0.x; acc[1][1] += a1 * b0.y; acc[1][2] += a1 * b0.z; acc[1][3] += a1 * b0.w;
            acc[1][4] += a1 * b1.x; acc[1][5] += a1 * b1.y; acc[1][6] += a1 * b1.z; acc[1][7] += a1 * b1.w;
            acc[2][0] += a2 * b0.x; acc[2][1] += a2 * b0.y; acc[2][2] += a2 * b0.z; acc[2][3] += a2 * b0.w;
            acc[2][4] += a2 * b1.x; acc[2][5] += a2 * b1.y; acc[2][6] += a2 * b1.z; acc[2][7] += a2 * b1.w;
            acc[3][0] += a3 * b0.x; acc[3][1] += a3 * b0.y; acc[3][2] += a3 * b0.z; acc[3][3] += a3 * b0.w;
            acc[3][4] += a3 * b1.x; acc[3][5] += a3 * b1.y; acc[3][6] += a3 * b1.z; acc[3][7] += a3 * b1.w;
        }
    }

    // epilogue: g_hw = hw ; g_agg = bias + hw * dinv^2
#pragma unroll
    for (int i = 0; i < 4; i++) {
        int r = block_row + ty * 4 + i;
        if (r >= N_NODES) continue;
        float s = sDinv2[ty * 4 + i];
        float4 h0 = make_float4(acc[i][0], acc[i][1], acc[i][2], acc[i][3]);
        float4 h1 = make_float4(acc[i][4], acc[i][5], acc[i][6], acc[i][7]);
        float* hw = g_hw + (size_t)r * HID + tx * 8;
        *(float4*)(hw)     = h0;
        *(float4*)(hw + 4) = h1;
        int c = tx * 8;
        float4 a0 = make_float4(sBias[c]     + h0.x * s, sBias[c + 1] + h0.y * s,
                                sBias[c + 2] + h0.z * s, sBias[c + 3] + h0.w * s);
        float4 a1 = make_float4(sBias[c + 4] + h1.x * s, sBias[c + 5] + h1.y * s,
                                sBias[c + 6] + h1.z * s, sBias[c + 7] + h1.w * s);
        float* ag = g_agg + (size_t)r * HID + tx * 8;
        *(float4*)(ag)     = a0;
        *(float4*)(ag + 4) = a1;
    }
}

// ---------------- edge scatter: 16 lanes per edge, vectorized REDG --------
__global__ void k_scatter(const int* __restrict__ src,
                          const int* __restrict__ dst, int E) {
    int t = blockIdx.x * blockDim.x + threadIdx.x;
    int e = t >> 4;
    if (e >= E) return;
    int l = t & 15;
    int s = src[e];
    int d = dst[e];
    float nrm = g_dinv[s] * g_dinv[d];
    float4 v = *(((const float4*)(g_hw + (size_t)s * HID)) + l);
    v.x *= nrm; v.y *= nrm; v.z *= nrm; v.w *= nrm;
    float* a = (float*)(((float4*)(g_agg + (size_t)d * HID)) + l);
    asm volatile("red.global.add.v4.f32 [%0], {%1, %2, %3, %4};"
                 :: "l"(a), "f"(v.x), "f"(v.y), "f"(v.z), "f"(v.w) : "memory");
}

// ---------------- batch-norm stats --------------------------------------
__global__ void k_zero_stats() {
    if (threadIdx.x < 2 * HID) g_stats[threadIdx.x] = 0.0f;
}

__global__ void k_reduce_stats() {
    __shared__ float ss[256], sq[256];
    int j  = threadIdx.x & 63;       // channel
    int rg = threadIdx.x >> 6;       // row group (0..3)
    float s = 0.0f, q = 0.0f;
    for (int r = blockIdx.x * 4 + rg; r < N_NODES; r += gridDim.x * 4) {
        float v = g_agg[(size_t)r * HID + j];
        s += v; q += v * v;
    }
    ss[threadIdx.x] = s; sq[threadIdx.x] = q;
    __syncthreads();
    if (threadIdx.x < 64) {
        float S = ss[threadIdx.x] + ss[threadIdx.x + 64] + ss[threadIdx.x + 128] + ss[threadIdx.x + 192];
        float Q = sq[threadIdx.x] + sq[threadIdx.x + 64] + sq[threadIdx.x + 128] + sq[threadIdx.x + 192];
        atomicAdd(&g_stats[j], S);
        atomicAdd(&g_stats[HID + j], Q);
    }
}

__global__ void k_bn_coef(const float* __restrict__ g, const float* __restrict__ bt) {
    int j = threadIdx.x;
    if (j >= HID) return;
    const float invN = 1.0f / (float)N_NODES;
    float mu  = g_stats[j] * invN;
    float var = g_stats[HID + j] * invN - mu * mu;
    float sc  = rsqrtf(var + EPS) * g[j];
    g_bnc[j]       = sc;
    g_bnc[HID + j] = bt[j] - mu * sc;
}

// ---------------- MLP head (BN+ReLU fused on input) ----------------------
__global__ void k_mlp(const float* __restrict__ lw1, const float* __restrict__ lb1,
                      const float* __restrict__ lw2, const float* __restrict__ lb2,
                      float* __restrict__ out) {
    __shared__ float sW1[64 * 32];
    __shared__ float sW2[32];
    __shared__ float sB1[32];
    __shared__ float sSc[64], sSh[64];
    __shared__ float sB2;
    for (int i = threadIdx.x; i < 64 * 32; i += blockDim.x) sW1[i] = lw1[i];
    if (threadIdx.x < 32) { sW2[threadIdx.x] = lw2[threadIdx.x]; sB1[threadIdx.x] = lb1[threadIdx.x]; }
    if (threadIdx.x < 64) { sSc[threadIdx.x] = g_bnc[threadIdx.x]; sSh[threadIdx.x] = g_bnc[64 + threadIdx.x]; }
    if (threadIdx.x == 0) sB2 = lb2[0];
    __syncthreads();

    int n = blockIdx.x * blockDim.x + threadIdx.x;
    if (n >= N_NODES) return;

    float t[32];
#pragma unroll
    for (int j = 0; j < 32; j++) t[j] = sB1[j];
    const float* a = g_agg + (size_t)n * HID;
    for (int k = 0; k < 64; k++) {
        float v = fmaxf(a[k] * sSc[k] + sSh[k], 0.f);
#pragma unroll
        for (int j = 0; j < 32; j++) t[j] += v * sW1[k * 32 + j];
    }
    float o = sB2;
#pragma unroll
    for (int j = 0; j < 32; j++) {
        float r = t[j] > 0.0f ? t[j] : 0.0f;
        o += r * sW2[j];
    }
    out[n] = o;
}

// ---------------- driver --------------------------------------------------
extern "C" void kernel_launch(void* const* d_in, const int* in_sizes, int n_in,
                              void* d_out, int out_size) {
    const float* x   = (const float*)d_in[0];
    const int*   ei  = (const int*)d_in[1];     // JAX downgrades int64->int32
    int E = in_sizes[1] / 2;
    const int* src = ei;
    const int* dst = ei + E;

    const float* W[3]  = { (const float*)d_in[2],  (const float*)d_in[6],  (const float*)d_in[10] };
    const float* B[3]  = { (const float*)d_in[3],  (const float*)d_in[7],  (const float*)d_in[11] };
    const float* G[3]  = { (const float*)d_in[4],  (const float*)d_in[8],  (const float*)d_in[12] };
    const float* BT[3] = { (const float*)d_in[5],  (const float*)d_in[9],  (const float*)d_in[13] };
    const float* lw1 = (const float*)d_in[14];
    const float* lb1 = (const float*)d_in[15];
    const float* lw2 = (const float*)d_in[16];
    const float* lb2 = (const float*)d_in[17];
    float* out = (float*)d_out;

    k_init_deg  <<<(N_NODES + 255) / 256, 256>>>();
    k_count_deg <<<(E + 255) / 256, 256>>>(dst, E);
    k_finish_deg<<<(N_NODES + 255) / 256, 256>>>();

    int gemm_grid = (N_NODES + 127) / 128;
    for (int l = 0; l < 3; l++) {
        int fi = (l == 0) ? 128 : HID;
        k_gemm_fused<<<gemm_grid, 256>>>(x, W[l], B[l], fi, l == 0 ? 0 : 1);
        k_scatter<<<((size_t)E * 16 + 255) / 256, 256>>>(src, dst, E);
        k_zero_stats<<<1, 2 * HID>>>();
        k_reduce_stats<<<512, 256>>>();
        k_bn_coef<<<1, HID>>>(G[l], BT[l]);
    }

    k_mlp<<<(N_NODES + 255) / 256, 256>>>(lw1, lb1, lw2, lb2, out);
}

// round 9
// speedup vs baseline: 1.4957x; 1.1472x over previous
#include <cuda_runtime.h>

#define N_NODES 100000
#define E_CAP   2000000
#define HID 64
#define EPS 1e-5f

// Scratch (allocation-free rule: __device__ globals)
__device__ float g_dinv[N_NODES];              // rsqrt(1+deg)
__device__ int   g_degi[N_NODES];              // int in-degree (no self loop)
__device__ int   g_cur [N_NODES];              // fill cursors
__device__ int   g_rowptr[N_NODES + 1];        // CSR row pointers (by dst)
__device__ int   g_csr[E_CAP];                 // CSR src indices
__device__ float g_p  [N_NODES * HID];         // p = (act(h) @ W) * dinv[row]
__device__ float g_agg[N_NODES * HID];         // aggregated (pre-BN), next-layer input
__device__ float g_stats[2 * HID];             // per-channel sum / sumsq
__device__ float g_bnc[2 * HID];               // per-channel BN (scale, shift)

// ---------------- degree / CSR build ----------------
__global__ void k_zero_idx() {
    int i = blockIdx.x * blockDim.x + threadIdx.x;
    if (i < N_NODES) { g_degi[i] = 0; g_cur[i] = 0; }
}

__global__ void k_count_deg(const int* __restrict__ dst, int E) {
    int i = blockIdx.x * blockDim.x + threadIdx.x;
    if (i < E) atomicAdd(&g_degi[dst[i]], 1);
}

__global__ void k_finish_deg() {
    int i = blockIdx.x * blockDim.x + threadIdx.x;
    if (i < N_NODES) g_dinv[i] = rsqrtf((float)(1 + g_degi[i]));   // self loop
}

// single-block exclusive scan: rowptr[i] = sum_{j<i} degi[j], rowptr[N]=E
__global__ void k_scan() {
    __shared__ int ssum[1024];
    const int C = (N_NODES + 1023) / 1024;     // 98
    int t = threadIdx.x;
    int base = t * C;
    int s = 0;
    for (int i = base; i < base + C && i < N_NODES; i++) s += g_degi[i];
    ssum[t] = s;
    __syncthreads();
    // Hillis-Steele inclusive scan
    for (int off = 1; off < 1024; off <<= 1) {
        int v = (t >= off) ? ssum[t - off] : 0;
        __syncthreads();
        ssum[t] += v;
        __syncthreads();
    }
    int run = (t == 0) ? 0 : ssum[t - 1];
    for (int i = base; i < base + C && i <= N_NODES; i++) {
        g_rowptr[i] = run;
        if (i < N_NODES) run += g_degi[i];
    }
}

__global__ void k_fill(const int* __restrict__ src, const int* __restrict__ dst, int E) {
    int e = blockIdx.x * blockDim.x + threadIdx.x;
    if (e >= E) return;
    int d = dst[e];
    int pos = atomicAdd(&g_cur[d], 1);
    g_csr[g_rowptr[d] + pos] = src[e];
}

// ---------------- fused GEMM ----------------------------------------------
// p = act(in) @ W * dinv[row]
// act = identity (layer 0, in = x) or BN+ReLU via g_bnc (layers 1,2, in = g_agg).
// BM=128 rows, BN=64 cols, BK=32. 256 threads, each 4 rows x 8 cols.
__global__ void __launch_bounds__(256, 2)
k_gemm_fused(const float* __restrict__ xin, const float* __restrict__ W,
             int fi, int use_bn)
{
    __shared__ float sA[128 * 36];   // [row][k] padded to 36
    __shared__ float sW[32 * 64];    // [k][col]
    __shared__ float sDinv[128];
    __shared__ float sSc[64], sSh[64];

    const float* in = use_bn ? (const float*)g_agg : xin;

    int tid = threadIdx.x;
    int block_row = blockIdx.x * 128;

    if (use_bn && tid < 64) { sSc[tid] = g_bnc[tid]; sSh[tid] = g_bnc[64 + tid]; }
    if (tid < 128) {
        int r = block_row + tid;
        sDinv[tid] = (r < N_NODES) ? g_dinv[r] : 0.0f;
    }

    float acc[4][8];
#pragma unroll
    for (int i = 0; i < 4; i++)
#pragma unroll
        for (int j = 0; j < 8; j++) acc[i][j] = 0.0f;

    int ty = tid >> 3;            // 0..31 -> rows ty*4..+4
    int tx = tid & 7;             // 0..7  -> cols tx*8..+8

    for (int k0 = 0; k0 < fi; k0 += 32) {
        __syncthreads();          // also orders sSc/sSh/sDinv init on 1st iter
        for (int idx = tid; idx < 128 * 8; idx += 256) {
            int row = idx >> 3;
            int c4  = (idx & 7) * 4;
            int rg  = block_row + row;
            float4 v = make_float4(0.f, 0.f, 0.f, 0.f);
            if (rg < N_NODES)
                v = *(const float4*)(in + (size_t)rg * fi + k0 + c4);
            if (use_bn) {
                int c = k0 + c4;
                v.x = fmaxf(v.x * sSc[c]     + sSh[c],     0.f);
                v.y = fmaxf(v.y * sSc[c + 1] + sSh[c + 1], 0.f);
                v.z = fmaxf(v.z * sSc[c + 2] + sSh[c + 2], 0.f);
                v.w = fmaxf(v.w * sSc[c + 3] + sSh[c + 3], 0.f);
            }
            *(float4*)(sA + row * 36 + c4) = v;
        }
        for (int idx = tid; idx < 32 * 16; idx += 256) {
            int row = idx >> 4;
            int c4  = (idx & 15) * 4;
            *(float4*)(sW + row * 64 + c4) =
                *(const float4*)(W + (size_t)(k0 + row) * 64 + c4);
        }
        __syncthreads();

#pragma unroll
        for (int k = 0; k < 32; k++) {
            float4 b0 = *(const float4*)(sW + k * 64 + tx * 8);
            float4 b1 = *(const float4*)(sW + k * 64 + tx * 8 + 4);
            float a0 = sA[(ty * 4 + 0) * 36 + k];
            float a1 = sA[(ty * 4 + 1) * 36 + k];
            float a2 = sA[(ty * 4 + 2) * 36 + k];
            float a3 = sA[(ty * 4 + 3) * 36 + k];
            acc[0][0] += a0 * b0.x; acc[0][1] += a0 * b0.y; acc[0][2] += a0 * b0.z; acc[0][3] += a0 * b0.w;
            acc[0][4] += a0 * b1.x; acc[0][5] += a0 * b1.y; acc[0][6] += a0 * b1.z; acc[0][7] += a0 * b1.w;
            acc[1][0] += a1 * b0.x; acc[1][1] += a1 * b0.y; acc[1][2] += a1 * b0.z; acc[1][3] += a1 * b0.w;
            acc[1][4] += a1 * b1.x; acc[1][5] += a1 * b1.y; acc[1][6] += a1 * b1.z; acc[1][7] += a1 * b1.w;
            acc[2][0] += a2 * b0.x; acc[2][1] += a2 * b0.y; acc[2][2] += a2 * b0.z; acc[2][3] += a2 * b0.w;
            acc[2][4] += a2 * b1.x; acc[2][5] += a2 * b1.y; acc[2][6] += a2 * b1.z; acc[2][7] += a2 * b1.w;
            acc[3][0] += a3 * b0.x; acc[3][1] += a3 * b0.y; acc[3][2] += a3 * b0.z; acc[3][3] += a3 * b0.w;
            acc[3][4] += a3 * b1.x; acc[3][5] += a3 * b1.y; acc[3][6] += a3 * b1.z; acc[3][7] += a3 * b1.w;
        }
    }

    // epilogue: p = hw * dinv[row]
#pragma unroll
    for (int i = 0; i < 4; i++) {
        int r = block_row + ty * 4 + i;
        if (r >= N_NODES) continue;
        float dv = sDinv[ty * 4 + i];
        float* pp = g_p + (size_t)r * HID + tx * 8;
        *(float4*)(pp)     = make_float4(acc[i][0] * dv, acc[i][1] * dv, acc[i][2] * dv, acc[i][3] * dv);
        *(float4*)(pp + 4) = make_float4(acc[i][4] * dv, acc[i][5] * dv, acc[i][6] * dv, acc[i][7] * dv);
    }
}

// ---------------- CSR aggregation: warp per dst node ----------------------
// agg[d] = bias + dinv[d] * ( sum_{s in in(d)} p[s] + p[d] )
__global__ void __launch_bounds__(256)
k_aggregate(const float* __restrict__ bias) {
    int warp = (blockIdx.x * blockDim.x + threadIdx.x) >> 5;
    if (warp >= N_NODES) return;
    int lane = threadIdx.x & 31;
    int half = lane >> 4;       // 0 or 1 (processes even/odd edges)
    int l    = lane & 15;       // float4 slice: channels l*4..l*4+3
    int d = warp;

    int beg = g_rowptr[d], end = g_rowptr[d + 1];

    float4 acc;
    if (half == 0) {            // self loop contribution p[d]
        acc = ((const float4*)(g_p + (size_t)d * HID))[l];
    } else {
        acc = make_float4(0.f, 0.f, 0.f, 0.f);
    }

    for (int e = beg + half; e < end; e += 2) {
        int s = g_csr[e];
        float4 v = ((const float4*)(g_p + (size_t)s * HID))[l];
        acc.x += v.x; acc.y += v.y; acc.z += v.z; acc.w += v.w;
    }

    // combine the two halves (lane l += lane l+16)
    acc.x += __shfl_down_sync(0xffffffffu, acc.x, 16);
    acc.y += __shfl_down_sync(0xffffffffu, acc.y, 16);
    acc.z += __shfl_down_sync(0xffffffffu, acc.z, 16);
    acc.w += __shfl_down_sync(0xffffffffu, acc.w, 16);

    if (half == 0) {
        float dv = g_dinv[d];
        float4 b = ((const float4*)bias)[l];
        float4 r = make_float4(b.x + dv * acc.x, b.y + dv * acc.y,
                               b.z + dv * acc.z, b.w + dv * acc.w);
        ((float4*)(g_agg + (size_t)d * HID))[l] = r;
    }
}

// ---------------- batch-norm stats --------------------------------------
__global__ void k_zero_stats() {
    if (threadIdx.x < 2 * HID) g_stats[threadIdx.x] = 0.0f;
}

__global__ void k_reduce_stats() {
    __shared__ float ss[256], sq[256];
    int j  = threadIdx.x & 63;       // channel
    int rg = threadIdx.x >> 6;       // row group (0..3)
    float s = 0.0f, q = 0.0f;
    for (int r = blockIdx.x * 4 + rg; r < N_NODES; r += gridDim.x * 4) {
        float v = g_agg[(size_t)r * HID + j];
        s += v; q += v * v;
    }
    ss[threadIdx.x] = s; sq[threadIdx.x] = q;
    __syncthreads();
    if (threadIdx.x < 64) {
        float S = ss[threadIdx.x] + ss[threadIdx.x + 64] + ss[threadIdx.x + 128] + ss[threadIdx.x + 192];
        float Q = sq[threadIdx.x] + sq[threadIdx.x + 64] + sq[threadIdx.x + 128] + sq[threadIdx.x + 192];
        atomicAdd(&g_stats[j], S);
        atomicAdd(&g_stats[HID + j], Q);
    }
}

__global__ void k_bn_coef(const float* __restrict__ g, const float* __restrict__ bt) {
    int j = threadIdx.x;
    if (j >= HID) return;
    const float invN = 1.0f / (float)N_NODES;
    float mu  = g_stats[j] * invN;
    float var = g_stats[HID + j] * invN - mu * mu;
    float sc  = rsqrtf(var + EPS) * g[j];
    g_bnc[j]       = sc;
    g_bnc[HID + j] = bt[j] - mu * sc;
}

// ---------------- MLP head (BN+ReLU fused on input) ----------------------
__global__ void k_mlp(const float* __restrict__ lw1, const float* __restrict__ lb1,
                      const float* __restrict__ lw2, const float* __restrict__ lb2,
                      float* __restrict__ out) {
    __shared__ float sW1[64 * 32];
    __shared__ float sW2[32];
    __shared__ float sB1[32];
    __shared__ float sSc[64], sSh[64];
    __shared__ float sB2;
    for (int i = threadIdx.x; i < 64 * 32; i += blockDim.x) sW1[i] = lw1[i];
    if (threadIdx.x < 32) { sW2[threadIdx.x] = lw2[threadIdx.x]; sB1[threadIdx.x] = lb1[threadIdx.x]; }
    if (threadIdx.x < 64) { sSc[threadIdx.x] = g_bnc[threadIdx.x]; sSh[threadIdx.x] = g_bnc[64 + threadIdx.x]; }
    if (threadIdx.x == 0) sB2 = lb2[0];
    __syncthreads();

    int n = blockIdx.x * blockDim.x + threadIdx.x;
    if (n >= N_NODES) return;

    float t[32];
#pragma unroll
    for (int j = 0; j < 32; j++) t[j] = sB1[j];
    const float* a = g_agg + (size_t)n * HID;
    for (int k = 0; k < 64; k++) {
        float v = fmaxf(a[k] * sSc[k] + sSh[k], 0.f);
#pragma unroll
        for (int j = 0; j < 32; j++) t[j] += v * sW1[k * 32 + j];
    }
    float o = sB2;
#pragma unroll
    for (int j = 0; j < 32; j++) {
        float r = t[j] > 0.0f ? t[j] : 0.0f;
        o += r * sW2[j];
    }
    out[n] = o;
}

// ---------------- driver --------------------------------------------------
extern "C" void kernel_launch(void* const* d_in, const int* in_sizes, int n_in,
                              void* d_out, int out_size) {
    const float* x   = (const float*)d_in[0];
    const int*   ei  = (const int*)d_in[1];     // JAX downgrades int64->int32
    int E = in_sizes[1] / 2;
    const int* src = ei;
    const int* dst = ei + E;

    const float* W[3]  = { (const float*)d_in[2],  (const float*)d_in[6],  (const float*)d_in[10] };
    const float* B[3]  = { (const float*)d_in[3],  (const float*)d_in[7],  (const float*)d_in[11] };
    const float* G[3]  = { (const float*)d_in[4],  (const float*)d_in[8],  (const float*)d_in[12] };
    const float* BT[3] = { (const float*)d_in[5],  (const float*)d_in[9],  (const float*)d_in[13] };
    const float* lw1 = (const float*)d_in[14];
    const float* lb1 = (const float*)d_in[15];
    const float* lw2 = (const float*)d_in[16];
    const float* lb2 = (const float*)d_in[17];
    float* out = (float*)d_out;

    // CSR build (per launch; edge fill order nondeterministic -> only last-ulp
    // variation in fp32 sums, well inside 1e-3 tolerance)
    k_zero_idx  <<<(N_NODES + 255) / 256, 256>>>();
    k_count_deg <<<(E + 255) / 256, 256>>>(dst, E);
    k_finish_deg<<<(N_NODES + 255) / 256, 256>>>();
    k_scan      <<<1, 1024>>>();
    k_fill      <<<(E + 255) / 256, 256>>>(src, dst, E);

    int gemm_grid = (N_NODES + 127) / 128;
    int agg_grid  = (N_NODES * 32 + 255) / 256;
    for (int l = 0; l < 3; l++) {
        int fi = (l == 0) ? 128 : HID;
        k_gemm_fused<<<gemm_grid, 256>>>(x, W[l], fi, l == 0 ? 0 : 1);
        k_aggregate<<<agg_grid, 256>>>(B[l]);
        k_zero_stats<<<1, 2 * HID>>>();
        k_reduce_stats<<<512, 256>>>();
        k_bn_coef<<<1, HID>>>(G[l], BT[l]);
    }

    k_mlp<<<(N_NODES + 255) / 256, 256>>>(lw1, lb1, lw2, lb2, out);
}

// round 10
// speedup vs baseline: 1.8519x; 1.2381x over previous
#include <cuda_runtime.h>

#define N_NODES 100000
#define E_CAP   2000000
#define HID 64
#define EPS 1e-5f

#define SCAN_CHUNK 1024
#define SCAN_NBLK  ((N_NODES + SCAN_CHUNK - 1) / SCAN_CHUNK)   // 98

// Scratch (allocation-free rule: __device__ globals)
__device__ float g_dinv[N_NODES];              // rsqrt(1+deg)
__device__ int   g_degi[N_NODES];              // int in-degree (no self loop)
__device__ int   g_cur [N_NODES];              // fill cursors
__device__ int   g_rowptr[N_NODES + 1];        // CSR row pointers (by dst)
__device__ int   g_csr[E_CAP];                 // CSR src indices
__device__ int   g_blocksum[SCAN_NBLK];        // scan phase-1 partials
__device__ int   g_blockoff[SCAN_NBLK];        // scan phase-2 offsets
__device__ float g_p  [N_NODES * HID];         // p = (act(h) @ W) * dinv[row]
__device__ float g_agg[N_NODES * HID];         // aggregated (pre-BN), next-layer input
__device__ float g_stats[2 * HID];             // per-channel sum / sumsq
__device__ float g_bnc[2 * HID];               // per-channel BN (scale, shift)

// ---------------- degree / CSR build ----------------
__global__ void k_zero_idx() {
    int i = blockIdx.x * blockDim.x + threadIdx.x;
    if (i < N_NODES) { g_degi[i] = 0; g_cur[i] = 0; }
}

__global__ void k_count_deg(const int* __restrict__ dst, int E) {
    int i = blockIdx.x * blockDim.x + threadIdx.x;
    if (i < E) atomicAdd(&g_degi[dst[i]], 1);
}

__global__ void k_finish_deg() {
    int i = blockIdx.x * blockDim.x + threadIdx.x;
    if (i < N_NODES) g_dinv[i] = rsqrtf((float)(1 + g_degi[i]));   // self loop
}

// ---- 3-phase device-wide exclusive scan of g_degi -> g_rowptr ----
// Phase 1: per-block chunk sums (256 thr, 4 elems each)
__global__ void k_scan_p1() {
    __shared__ int red[256];
    int t = threadIdx.x;
    int base = blockIdx.x * SCAN_CHUNK + t * 4;
    int s = 0;
#pragma unroll
    for (int i = 0; i < 4; i++) {
        int idx = base + i;
        if (idx < N_NODES) s += g_degi[idx];
    }
    red[t] = s;
    __syncthreads();
    for (int off = 128; off > 0; off >>= 1) {
        if (t < off) red[t] += red[t + off];
        __syncthreads();
    }
    if (t == 0) g_blocksum[blockIdx.x] = red[0];
}

// Phase 2: exclusive scan of the 98 partials (single tiny block)
__global__ void k_scan_p2() {
    __shared__ int s[SCAN_NBLK];
    int t = threadIdx.x;
    if (t < SCAN_NBLK) s[t] = g_blocksum[t];
    __syncthreads();
    if (t == 0) {
        int run = 0;
        for (int i = 0; i < SCAN_NBLK; i++) { int v = s[i]; s[i] = run; run += v; }
    }
    __syncthreads();
    if (t < SCAN_NBLK) g_blockoff[t] = s[t];
}

// Phase 3: block-local exclusive scan + offset -> rowptr
__global__ void k_scan_p3(int E) {
    __shared__ int ssum[256];
    int t = threadIdx.x;
    int base = blockIdx.x * SCAN_CHUNK + t * 4;
    int d[4];
    int s = 0;
#pragma unroll
    for (int i = 0; i < 4; i++) {
        int idx = base + i;
        d[i] = (idx < N_NODES) ? g_degi[idx] : 0;
        s += d[i];
    }
    ssum[t] = s;
    __syncthreads();
    // Hillis-Steele inclusive over 256
    for (int off = 1; off < 256; off <<= 1) {
        int v = (t >= off) ? ssum[t - off] : 0;
        __syncthreads();
        ssum[t] += v;
        __syncthreads();
    }
    int run = g_blockoff[blockIdx.x] + ((t == 0) ? 0 : ssum[t - 1]);
#pragma unroll
    for (int i = 0; i < 4; i++) {
        int idx = base + i;
        if (idx < N_NODES) { g_rowptr[idx] = run; run += d[i]; }
    }
    if (blockIdx.x == gridDim.x - 1 && t == 255) g_rowptr[N_NODES] = E;
}

__global__ void k_fill(const int* __restrict__ src, const int* __restrict__ dst, int E) {
    int e = blockIdx.x * blockDim.x + threadIdx.x;
    if (e >= E) return;
    int d = dst[e];
    int pos = atomicAdd(&g_cur[d], 1);
    g_csr[g_rowptr[d] + pos] = src[e];
}

// ---------------- fused GEMM ----------------------------------------------
// p = act(in) @ W * dinv[row]
// act = identity (layer 0, in = x) or BN+ReLU via g_bnc (layers 1,2, in = g_agg).
// BM=128 rows, BN=64 cols, BK=32. 256 threads, each 4 rows x 8 cols.
__global__ void __launch_bounds__(256, 2)
k_gemm_fused(const float* __restrict__ xin, const float* __restrict__ W,
             int fi, int use_bn)
{
    __shared__ float sA[128 * 36];   // [row][k] padded to 36
    __shared__ float sW[32 * 64];    // [k][col]
    __shared__ float sDinv[128];
    __shared__ float sSc[64], sSh[64];

    const float* in = use_bn ? (const float*)g_agg : xin;

    int tid = threadIdx.x;
    int block_row = blockIdx.x * 128;

    if (use_bn && tid < 64) { sSc[tid] = g_bnc[tid]; sSh[tid] = g_bnc[64 + tid]; }
    if (tid < 128) {
        int r = block_row + tid;
        sDinv[tid] = (r < N_NODES) ? g_dinv[r] : 0.0f;
    }

    float acc[4][8];
#pragma unroll
    for (int i = 0; i < 4; i++)
#pragma unroll
        for (int j = 0; j < 8; j++) acc[i][j] = 0.0f;

    int ty = tid >> 3;            // 0..31 -> rows ty*4..+4
    int tx = tid & 7;             // 0..7  -> cols tx*8..+8

    for (int k0 = 0; k0 < fi; k0 += 32) {
        __syncthreads();          // also orders sSc/sSh/sDinv init on 1st iter
        for (int idx = tid; idx < 128 * 8; idx += 256) {
            int row = idx >> 3;
            int c4  = (idx & 7) * 4;
            int rg  = block_row + row;
            float4 v = make_float4(0.f, 0.f, 0.f, 0.f);
            if (rg < N_NODES)
                v = *(const float4*)(in + (size_t)rg * fi + k0 + c4);
            if (use_bn) {
                int c = k0 + c4;
                v.x = fmaxf(v.x * sSc[c]     + sSh[c],     0.f);
                v.y = fmaxf(v.y * sSc[c + 1] + sSh[c + 1], 0.f);
                v.z = fmaxf(v.z * sSc[c + 2] + sSh[c + 2], 0.f);
                v.w = fmaxf(v.w * sSc[c + 3] + sSh[c + 3], 0.f);
            }
            *(float4*)(sA + row * 36 + c4) = v;
        }
        for (int idx = tid; idx < 32 * 16; idx += 256) {
            int row = idx >> 4;
            int c4  = (idx & 15) * 4;
            *(float4*)(sW + row * 64 + c4) =
                *(const float4*)(W + (size_t)(k0 + row) * 64 + c4);
        }
        __syncthreads();

#pragma unroll
        for (int k = 0; k < 32; k++) {
            float4 b0 = *(const float4*)(sW + k * 64 + tx * 8);
            float4 b1 = *(const float4*)(sW + k * 64 + tx * 8 + 4);
            float a0 = sA[(ty * 4 + 0) * 36 + k];
            float a1 = sA[(ty * 4 + 1) * 36 + k];
            float a2 = sA[(ty * 4 + 2) * 36 + k];
            float a3 = sA[(ty * 4 + 3) * 36 + k];
            acc[0][0] += a0 * b0.x; acc[0][1] += a0 * b0.y; acc[0][2] += a0 * b0.z; acc[0][3] += a0 * b0.w;
            acc[0][4] += a0 * b1.x; acc[0][5] += a0 * b1.y; acc[0][6] += a0 * b1.z; acc[0][7] += a0 * b1.w;
            acc[1][0] += a1 * b0.x; acc[1][1] += a1 * b0.y; acc[1][2] += a1 * b0.z; acc[1][3] += a1 * b0.w;
            acc[1][4] += a1 * b1.x; acc[1][5] += a1 * b1.y; acc[1][6] += a1 * b1.z; acc[1][7] += a1 * b1.w;
            acc[2][0] += a2 * b0.x; acc[2][1] += a2 * b0.y; acc[2][2] += a2 * b0.z; acc[2][3] += a2 * b0.w;
            acc[2][4] += a2 * b1.x; acc[2][5] += a2 * b1.y; acc[2][6] += a2 * b1.z; acc[2][7] += a2 * b1.w;
            acc[3][0] += a3 * b0.x; acc[3][1] += a3 * b0.y; acc[3][2] += a3 * b0.z; acc[3][3] += a3 * b0.w;
            acc[3][4] += a3 * b1.x; acc[3][5] += a3 * b1.y; acc[3][6] += a3 * b1.z; acc[3][7] += a3 * b1.w;
        }
    }

    // epilogue: p = hw * dinv[row]
#pragma unroll
    for (int i = 0; i < 4; i++) {
        int r = block_row + ty * 4 + i;
        if (r >= N_NODES) continue;
        float dv = sDinv[ty * 4 + i];
        float* pp = g_p + (size_t)r * HID + tx * 8;
        *(float4*)(pp)     = make_float4(acc[i][0] * dv, acc[i][1] * dv, acc[i][2] * dv, acc[i][3] * dv);
        *(float4*)(pp + 4) = make_float4(acc[i][4] * dv, acc[i][5] * dv, acc[i][6] * dv, acc[i][7] * dv);
    }
}

// ---------------- CSR aggregation: warp per dst node ----------------------
// agg[d] = bias + dinv[d] * ( sum_{s in in(d)} p[s] + p[d] )
__global__ void __launch_bounds__(256)
k_aggregate(const float* __restrict__ bias) {
    int warp = (blockIdx.x * blockDim.x + threadIdx.x) >> 5;
    if (warp >= N_NODES) return;
    int lane = threadIdx.x & 31;
    int half = lane >> 4;       // 0 or 1 (processes even/odd edges)
    int l    = lane & 15;       // float4 slice: channels l*4..l*4+3
    int d = warp;

    int beg = g_rowptr[d], end = g_rowptr[d + 1];

    float4 acc;
    if (half == 0) {            // self loop contribution p[d]
        acc = ((const float4*)(g_p + (size_t)d * HID))[l];
    } else {
        acc = make_float4(0.f, 0.f, 0.f, 0.f);
    }

    for (int e = beg + half; e < end; e += 2) {
        int s = g_csr[e];
        float4 v = ((const float4*)(g_p + (size_t)s * HID))[l];
        acc.x += v.x; acc.y += v.y; acc.z += v.z; acc.w += v.w;
    }

    // combine the two halves (lane l += lane l+16)
    acc.x += __shfl_down_sync(0xffffffffu, acc.x, 16);
    acc.y += __shfl_down_sync(0xffffffffu, acc.y, 16);
    acc.z += __shfl_down_sync(0xffffffffu, acc.z, 16);
    acc.w += __shfl_down_sync(0xffffffffu, acc.w, 16);

    if (half == 0) {
        float dv = g_dinv[d];
        float4 b = ((const float4*)bias)[l];
        float4 r = make_float4(b.x + dv * acc.x, b.y + dv * acc.y,
                               b.z + dv * acc.z, b.w + dv * acc.w);
        ((float4*)(g_agg + (size_t)d * HID))[l] = r;
    }
}

// ---------------- batch-norm stats --------------------------------------
__global__ void k_zero_stats() {
    if (threadIdx.x < 2 * HID) g_stats[threadIdx.x] = 0.0f;
}

__global__ void k_reduce_stats() {
    __shared__ float ss[256], sq[256];
    int j  = threadIdx.x & 63;       // channel
    int rg = threadIdx.x >> 6;       // row group (0..3)
    float s = 0.0f, q = 0.0f;
    for (int r = blockIdx.x * 4 + rg; r < N_NODES; r += gridDim.x * 4) {
        float v = g_agg[(size_t)r * HID + j];
        s += v; q += v * v;
    }
    ss[threadIdx.x] = s; sq[threadIdx.x] = q;
    __syncthreads();
    if (threadIdx.x < 64) {
        float S = ss[threadIdx.x] + ss[threadIdx.x + 64] + ss[threadIdx.x + 128] + ss[threadIdx.x + 192];
        float Q = sq[threadIdx.x] + sq[threadIdx.x + 64] + sq[threadIdx.x + 128] + sq[threadIdx.x + 192];
        atomicAdd(&g_stats[j], S);
        atomicAdd(&g_stats[HID + j], Q);
    }
}

__global__ void k_bn_coef(const float* __restrict__ g, const float* __restrict__ bt) {
    int j = threadIdx.x;
    if (j >= HID) return;
    const float invN = 1.0f / (float)N_NODES;
    float mu  = g_stats[j] * invN;
    float var = g_stats[HID + j] * invN - mu * mu;
    float sc  = rsqrtf(var + EPS) * g[j];
    g_bnc[j]       = sc;
    g_bnc[HID + j] = bt[j] - mu * sc;
}

// ---------------- MLP head (BN+ReLU fused on input) ----------------------
__global__ void k_mlp(const float* __restrict__ lw1, const float* __restrict__ lb1,
                      const float* __restrict__ lw2, const float* __restrict__ lb2,
                      float* __restrict__ out) {
    __shared__ float sW1[64 * 32];
    __shared__ float sW2[32];
    __shared__ float sB1[32];
    __shared__ float sSc[64], sSh[64];
    __shared__ float sB2;
    for (int i = threadIdx.x; i < 64 * 32; i += blockDim.x) sW1[i] = lw1[i];
    if (threadIdx.x < 32) { sW2[threadIdx.x] = lw2[threadIdx.x]; sB1[threadIdx.x] = lb1[threadIdx.x]; }
    if (threadIdx.x < 64) { sSc[threadIdx.x] = g_bnc[threadIdx.x]; sSh[threadIdx.x] = g_bnc[64 + threadIdx.x]; }
    if (threadIdx.x == 0) sB2 = lb2[0];
    __syncthreads();

    int n = blockIdx.x * blockDim.x + threadIdx.x;
    if (n >= N_NODES) return;

    float t[32];
#pragma unroll
    for (int j = 0; j < 32; j++) t[j] = sB1[j];
    const float* a = g_agg + (size_t)n * HID;
    for (int k = 0; k < 64; k++) {
        float v = fmaxf(a[k] * sSc[k] + sSh[k], 0.f);
#pragma unroll
        for (int j = 0; j < 32; j++) t[j] += v * sW1[k * 32 + j];
    }
    float o = sB2;
#pragma unroll
    for (int j = 0; j < 32; j++) {
        float r = t[j] > 0.0f ? t[j] : 0.0f;
        o += r * sW2[j];
    }
    out[n] = o;
}

// ---------------- driver --------------------------------------------------
extern "C" void kernel_launch(void* const* d_in, const int* in_sizes, int n_in,
                              void* d_out, int out_size) {
    const float* x   = (const float*)d_in[0];
    const int*   ei  = (const int*)d_in[1];     // JAX downgrades int64->int32
    int E = in_sizes[1] / 2;
    const int* src = ei;
    const int* dst = ei + E;

    const float* W[3]  = { (const float*)d_in[2],  (const float*)d_in[6],  (const float*)d_in[10] };
    const float* B[3]  = { (const float*)d_in[3],  (const float*)d_in[7],  (const float*)d_in[11] };
    const float* G[3]  = { (const float*)d_in[4],  (const float*)d_in[8],  (const float*)d_in[12] };
    const float* BT[3] = { (const float*)d_in[5],  (const float*)d_in[9],  (const float*)d_in[13] };
    const float* lw1 = (const float*)d_in[14];
    const float* lb1 = (const float*)d_in[15];
    const float* lw2 = (const float*)d_in[16];
    const float* lb2 = (const float*)d_in[17];
    float* out = (float*)d_out;

    // CSR build (per launch; edge fill order nondeterministic -> only last-ulp
    // variation in fp32 sums, well inside 1e-3 tolerance)
    k_zero_idx  <<<(N_NODES + 255) / 256, 256>>>();
    k_count_deg <<<(E + 255) / 256, 256>>>(dst, E);
    k_finish_deg<<<(N_NODES + 255) / 256, 256>>>();
    k_scan_p1   <<<SCAN_NBLK, 256>>>();
    k_scan_p2   <<<1, 128>>>();
    k_scan_p3   <<<SCAN_NBLK, 256>>>(E);
    k_fill      <<<(E + 255) / 256, 256>>>(src, dst, E);

    int gemm_grid = (N_NODES + 127) / 128;
    int agg_grid  = (N_NODES * 32 + 255) / 256;
    for (int l = 0; l < 3; l++) {
        int fi = (l == 0) ? 128 : HID;
        k_gemm_fused<<<gemm_grid, 256>>>(x, W[l], fi, l == 0 ? 0 : 1);
        k_aggregate<<<agg_grid, 256>>>(B[l]);
        k_zero_stats<<<1, 2 * HID>>>();
        k_reduce_stats<<<512, 256>>>();
        k_bn_coef<<<1, HID>>>(G[l], BT[l]);
    }

    k_mlp<<<(N_NODES + 255) / 256, 256>>>(lw1, lb1, lw2, lb2, out);
}